// round 9
// baseline (speedup 1.0000x reference)
#include <cuda_runtime.h>
#include <cuda_bf16.h>
#include <cstdint>

#define D 128
#define VCAP 100000
#define CAP 128
#define TM_ROWS 64         // rows per tensor tile (M)
#define TC_THR 256         // 8 warps: 2 row groups (32 rows) x 4 col groups (32 cols)
#define KS 136             // bf16 row stride (128 + 8 pad) -> conflict-free LDSM

// ---------------- scratch ----------------
__device__ float g_h0[(size_t)VCAP * D];
__device__ float g_h1[(size_t)VCAP * D];
__device__ float g_y [(size_t)VCAP * D];
__device__ int   g_adj[(size_t)VCAP * CAP];
__device__ int   g_cnt[VCAP];
__device__ float g_dinv[VCAP];
__device__ float g_stats[3 * 2 * D];

// ---------------- helpers ----------------
__device__ __forceinline__ uint32_t smem_u32(const void* p) {
    return (uint32_t)__cvta_generic_to_shared(p);
}
__device__ __forceinline__ uint32_t pack_bf(float a, float b) {
    __nv_bfloat162 h = __floats2bfloat162_rn(a, b);
    return *reinterpret_cast<uint32_t*>(&h);
}
__device__ __forceinline__ void ldsm_x4(uint32_t addr, uint32_t r[4]) {
    asm volatile("ldmatrix.sync.aligned.m8n8.x4.shared.b16 {%0,%1,%2,%3}, [%4];"
                 : "=r"(r[0]), "=r"(r[1]), "=r"(r[2]), "=r"(r[3]) : "r"(addr));
}
__device__ __forceinline__ void mma_bf16(float c[4], const uint32_t a[4],
                                         uint32_t b0, uint32_t b1) {
    asm volatile(
        "mma.sync.aligned.m16n8k16.row.col.f32.bf16.bf16.f32 "
        "{%0,%1,%2,%3}, {%4,%5,%6,%7}, {%8,%9}, {%0,%1,%2,%3};"
        : "+f"(c[0]), "+f"(c[1]), "+f"(c[2]), "+f"(c[3])
        : "r"(a[0]), "r"(a[1]), "r"(a[2]), "r"(a[3]), "r"(b0), "r"(b1));
}

// ---------------- prologue kernels ----------------
__global__ void zero_kernel(int V) {
    int i = blockIdx.x * blockDim.x + threadIdx.x;
    if (i < V) g_cnt[i] = 0;
    if (i < 3 * 2 * D) g_stats[i] = 0.0f;
}

__global__ void build_adj(const int* __restrict__ edges, int E) {
    int e = blockIdx.x * blockDim.x + threadIdx.x;
    if (e >= E) return;
    int a = edges[2 * e];
    int b = edges[2 * e + 1];
    int pa = atomicAdd(&g_cnt[a], 1);
    if (pa < CAP) g_adj[(size_t)a * CAP + pa] = b;
    int pb = atomicAdd(&g_cnt[b], 1);
    if (pb < CAP) g_adj[(size_t)b * CAP + pb] = a;
}

__global__ void dinv_kernel(int V) {
    int i = blockIdx.x * blockDim.x + threadIdx.x;
    if (i < V) g_dinv[i] = 1.0f / (1.0f + (float)g_cnt[i]);
}

// ---------------- HMMA single-output GEMM (bf16x2 split, 3 terms) ----------------
// Even CTAs: h0 = f(x) @ W0^T + b0 ; Odd CTAs: h1 = f(x) @ W1^T + b1
// f = BN+ReLU of prev layer (l>0). 2 CTAs/SM -> independent barrier domains overlap.
__global__ void __launch_bounds__(TC_THR, 2)
gemm_dual_tc(const float* __restrict__ xext, int layer,
             const float* __restrict__ W0, const float* __restrict__ b0,
             const float* __restrict__ W1, const float* __restrict__ b1,
             const float* __restrict__ gammaPrev, const float* __restrict__ betaPrev,
             int V, float invV)
{
    extern __shared__ __align__(16) char smb[];
    __nv_bfloat16* Bhi = (__nv_bfloat16*)smb;                       // [128][KS]
    __nv_bfloat16* Blo = Bhi + 128 * KS;                            // [128][KS]
    __nv_bfloat16* Ahi = Blo + 128 * KS;                            // [64][KS]
    __nv_bfloat16* Alo = Ahi + TM_ROWS * KS;                        // [64][KS]

    __shared__ float s_sc[D], s_sh[D], s_bias[D];

    const float* x = (layer == 0) ? xext : g_y;
    const bool doNorm = (layer != 0);

    int nsel = blockIdx.x & 1;
    const float* W  = nsel ? W1 : W0;
    const float* bb = nsel ? b1 : b0;
    float* gout = nsel ? g_h1 : g_h0;

    int tid  = threadIdx.x;
    int wid  = tid >> 5;
    int lane = tid & 31;

    if (tid < D) {
        if (doNorm) {
            const float* st = g_stats + (layer - 1) * 2 * D;
            float mu  = st[tid] * invV;
            float var = st[D + tid] * invV - mu * mu;
            float rs  = rsqrtf(var + 1e-5f);
            float sc  = gammaPrev[tid] * rs;
            s_sc[tid] = sc;
            s_sh[tid] = betaPrev[tid] - mu * sc;
        }
        s_bias[tid] = bb[tid];
    }

    // --- convert W -> Bhi/Blo (once per block) ---
    for (int idx = tid; idx < 128 * 32; idx += TC_THR) {
        int n  = idx >> 5;
        int k4 = (idx & 31) * 4;
        float4 w = *(const float4*)(W + (size_t)n * D + k4);
        float h0 = __bfloat162float(__float2bfloat16_rn(w.x));
        float h1 = __bfloat162float(__float2bfloat16_rn(w.y));
        float h2 = __bfloat162float(__float2bfloat16_rn(w.z));
        float h3 = __bfloat162float(__float2bfloat16_rn(w.w));
        *(uint2*)(Bhi + n * KS + k4) = make_uint2(pack_bf(h0, h1), pack_bf(h2, h3));
        *(uint2*)(Blo + n * KS + k4) = make_uint2(pack_bf(w.x - h0, w.y - h1),
                                                  pack_bf(w.z - h2, w.w - h3));
    }

    // warp tiling: mw = row group (32 rows, 0..1), nw = col group (32 cols, 0..3)
    int mw = wid >> 2;
    int nw = wid & 3;
    int mrow0 = mw * 32;
    int ncolbase = nw * 32;

    // A ldmatrix addresses: two 16-row sets
    uint32_t aOffB = (uint32_t)(((mrow0 + (lane & 15)) * KS + (lane >> 4) * 8) * 2);
    uint32_t aHiAddr0 = smem_u32(Ahi) + aOffB;
    uint32_t aLoAddr0 = smem_u32(Alo) + aOffB;
    uint32_t aHiAddr1 = aHiAddr0 + 16 * KS * 2;
    uint32_t aLoAddr1 = aLoAddr0 + 16 * KS * 2;

    // B ldmatrix x4 addresses: 16 n-rows per load (2 n-groups of 8)
    uint32_t bOffB = (uint32_t)(((ncolbase + (lane & 15)) * KS + (lane >> 4) * 8) * 2);
    uint32_t bHiAddr = smem_u32(Bhi) + bOffB;
    uint32_t bLoAddr = smem_u32(Blo) + bOffB;

    int ncol = (lane & 3) * 2;

    int numTiles = (V + TM_ROWS - 1) / TM_ROWS;
    int tStride = gridDim.x >> 1;

    __syncthreads();   // B + params ready

    for (int t = blockIdx.x >> 1; t < numTiles; t += tStride) {
        int r0 = t * TM_ROWS;

        // --- convert x tile -> Ahi/Alo (fused BN+ReLU for layers 1,2) ---
        #pragma unroll
        for (int it = 0; it < 8; it++) {
            int f  = tid + it * TC_THR;
            int r  = f >> 5;
            int k4 = (f & 31) * 4;
            int row = r0 + r;
            float4 a = (row < V) ? *(const float4*)(x + (size_t)row * D + k4)
                                 : make_float4(0.f, 0.f, 0.f, 0.f);
            if (doNorm && row < V) {
                a.x = fmaxf(fmaf(a.x, s_sc[k4 + 0], s_sh[k4 + 0]), 0.f);
                a.y = fmaxf(fmaf(a.y, s_sc[k4 + 1], s_sh[k4 + 1]), 0.f);
                a.z = fmaxf(fmaf(a.z, s_sc[k4 + 2], s_sh[k4 + 2]), 0.f);
                a.w = fmaxf(fmaf(a.w, s_sc[k4 + 3], s_sh[k4 + 3]), 0.f);
            }
            float h0 = __bfloat162float(__float2bfloat16_rn(a.x));
            float h1 = __bfloat162float(__float2bfloat16_rn(a.y));
            float h2 = __bfloat162float(__float2bfloat16_rn(a.z));
            float h3 = __bfloat162float(__float2bfloat16_rn(a.w));
            *(uint2*)(Ahi + r * KS + k4) = make_uint2(pack_bf(h0, h1), pack_bf(h2, h3));
            *(uint2*)(Alo + r * KS + k4) = make_uint2(pack_bf(a.x - h0, a.y - h1),
                                                      pack_bf(a.z - h2, a.w - h3));
        }
        __syncthreads();

        // --- accumulators init to bias: acc[n][0..3] rowset0, [4..7] rowset1 ---
        float acc[4][8];
        #pragma unroll
        for (int n = 0; n < 4; n++) {
            float bx = s_bias[ncolbase + n * 8 + ncol];
            float by = s_bias[ncolbase + n * 8 + ncol + 1];
            acc[n][0] = bx; acc[n][1] = by; acc[n][2] = bx; acc[n][3] = by;
            acc[n][4] = bx; acc[n][5] = by; acc[n][6] = bx; acc[n][7] = by;
        }

        // --- main MMA loop: 8 k-chunks ---
        #pragma unroll
        for (int kc = 0; kc < 8; kc++) {
            uint32_t ahi0[4], alo0[4], ahi1[4], alo1[4];
            ldsm_x4(aHiAddr0 + kc * 32, ahi0);
            ldsm_x4(aLoAddr0 + kc * 32, alo0);
            ldsm_x4(aHiAddr1 + kc * 32, ahi1);
            ldsm_x4(aLoAddr1 + kc * 32, alo1);
            #pragma unroll
            for (int np = 0; np < 2; np++) {
                uint32_t bhi[4], blo[4];
                uint32_t boff = (uint32_t)(np * 16 * KS * 2 + kc * 32);
                ldsm_x4(bHiAddr + boff, bhi);
                ldsm_x4(bLoAddr + boff, blo);
                float* aE0 = acc[np * 2];
                float* aO0 = acc[np * 2 + 1];
                mma_bf16(aE0,     ahi0, bhi[0], bhi[2]);
                mma_bf16(aE0,     ahi0, blo[0], blo[2]);
                mma_bf16(aE0,     alo0, bhi[0], bhi[2]);
                mma_bf16(aO0,     ahi0, bhi[1], bhi[3]);
                mma_bf16(aO0,     ahi0, blo[1], blo[3]);
                mma_bf16(aO0,     alo0, bhi[1], bhi[3]);
                mma_bf16(aE0 + 4, ahi1, bhi[0], bhi[2]);
                mma_bf16(aE0 + 4, ahi1, blo[0], blo[2]);
                mma_bf16(aE0 + 4, alo1, bhi[0], bhi[2]);
                mma_bf16(aO0 + 4, ahi1, bhi[1], bhi[3]);
                mma_bf16(aO0 + 4, ahi1, blo[1], blo[3]);
                mma_bf16(aO0 + 4, alo1, bhi[1], bhi[3]);
            }
        }

        // --- epilogue: store ---
        int rA = r0 + mrow0 + (lane >> 2);
        #pragma unroll
        for (int n = 0; n < 4; n++) {
            int c = ncolbase + n * 8 + ncol;
            if (rA < V)      *(float2*)(gout + (size_t)rA * D + c)        = make_float2(acc[n][0], acc[n][1]);
            if (rA + 8 < V)  *(float2*)(gout + (size_t)(rA + 8) * D + c)  = make_float2(acc[n][2], acc[n][3]);
            if (rA + 16 < V) *(float2*)(gout + (size_t)(rA + 16) * D + c) = make_float2(acc[n][4], acc[n][5]);
            if (rA + 24 < V) *(float2*)(gout + (size_t)(rA + 24) * D + c) = make_float2(acc[n][6], acc[n][7]);
        }
        __syncthreads();   // MMA readers done before next conversion overwrites A
    }
}

// ---------------- aggregation + BN stats ----------------
__global__ void __launch_bounds__(256) agg_kernel(float* __restrict__ stats, int V)
{
    __shared__ float s_sum[D];
    __shared__ float s_sq[D];

    int tid  = threadIdx.x;
    int wid  = tid >> 5;
    int lane = tid & 31;
    int c0   = lane * 4;

    if (tid < D) { s_sum[tid] = 0.f; s_sq[tid] = 0.f; }
    __syncthreads();

    float4 psum = make_float4(0.f, 0.f, 0.f, 0.f);
    float4 psq  = make_float4(0.f, 0.f, 0.f, 0.f);

    int warpStride = gridDim.x * 8;
    for (int v = blockIdx.x * 8 + wid; v < V; v += warpStride) {
        float4 acc = *(const float4*)(g_h0 + (size_t)v * D + c0);
        int n = g_cnt[v];
        const int* ap = g_adj + (size_t)v * CAP;
        int e = 0;
        for (; e + 3 < n; e += 4) {
            int u0 = ap[e], u1 = ap[e + 1], u2 = ap[e + 2], u3 = ap[e + 3];
            float4 t0 = __ldg((const float4*)(g_h1 + (size_t)u0 * D + c0));
            float4 t1 = __ldg((const float4*)(g_h1 + (size_t)u1 * D + c0));
            float4 t2 = __ldg((const float4*)(g_h1 + (size_t)u2 * D + c0));
            float4 t3 = __ldg((const float4*)(g_h1 + (size_t)u3 * D + c0));
            acc.x += (t0.x + t1.x) + (t2.x + t3.x);
            acc.y += (t0.y + t1.y) + (t2.y + t3.y);
            acc.z += (t0.z + t1.z) + (t2.z + t3.z);
            acc.w += (t0.w + t1.w) + (t2.w + t3.w);
        }
        for (; e < n; e++) {
            int u = ap[e];
            float4 t = __ldg((const float4*)(g_h1 + (size_t)u * D + c0));
            acc.x += t.x; acc.y += t.y; acc.z += t.z; acc.w += t.w;
        }
        float dv = g_dinv[v];
        acc.x *= dv; acc.y *= dv; acc.z *= dv; acc.w *= dv;
        *(float4*)(g_y + (size_t)v * D + c0) = acc;

        psum.x += acc.x; psum.y += acc.y; psum.z += acc.z; psum.w += acc.w;
        psq.x  += acc.x * acc.x; psq.y += acc.y * acc.y;
        psq.z  += acc.z * acc.z; psq.w += acc.w * acc.w;
    }

    atomicAdd(&s_sum[c0 + 0], psum.x);
    atomicAdd(&s_sum[c0 + 1], psum.y);
    atomicAdd(&s_sum[c0 + 2], psum.z);
    atomicAdd(&s_sum[c0 + 3], psum.w);
    atomicAdd(&s_sq[c0 + 0],  psq.x);
    atomicAdd(&s_sq[c0 + 1],  psq.y);
    atomicAdd(&s_sq[c0 + 2],  psq.z);
    atomicAdd(&s_sq[c0 + 3],  psq.w);
    __syncthreads();

    if (tid < D) {
        atomicAdd(&stats[tid],     s_sum[tid]);
        atomicAdd(&stats[D + tid], s_sq[tid]);
    }
}

// ---------------- final BN + ReLU + residual -> out ----------------
__global__ void __launch_bounds__(256) norm_final(
    const float* __restrict__ stats,
    const float* __restrict__ gamma, const float* __restrict__ beta,
    const float* __restrict__ res,
    float* __restrict__ out, int V, float invV)
{
    __shared__ float s_scale[D];
    __shared__ float s_shift[D];

    int tid = threadIdx.x;
    if (tid < D) {
        float mu  = stats[tid] * invV;
        float var = stats[D + tid] * invV - mu * mu;
        float rs  = rsqrtf(var + 1e-5f);
        float sc  = gamma[tid] * rs;
        s_scale[tid] = sc;
        s_shift[tid] = beta[tid] - mu * sc;
    }
    __syncthreads();

    int total = V * (D / 4);
    for (int f = blockIdx.x * blockDim.x + tid; f < total; f += gridDim.x * blockDim.x) {
        int c = (f & 31) * 4;
        float4 t = *(const float4*)(g_y + (size_t)f * 4);
        float4 r = *(const float4*)(res + (size_t)f * 4);
        float4 o;
        o.x = fmaxf(fmaf(t.x, s_scale[c + 0], s_shift[c + 0]) + r.x, 0.f);
        o.y = fmaxf(fmaf(t.y, s_scale[c + 1], s_shift[c + 1]) + r.y, 0.f);
        o.z = fmaxf(fmaf(t.z, s_scale[c + 2], s_shift[c + 2]) + r.z, 0.f);
        o.w = fmaxf(fmaf(t.w, s_scale[c + 3], s_shift[c + 3]) + r.w, 0.f);
        *(float4*)(out + (size_t)f * 4) = o;
    }
}

// ---------------- launch ----------------
extern "C" void kernel_launch(void* const* d_in, const int* in_sizes, int n_in,
                              void* d_out, int out_size)
{
    const float* features = (const float*)d_in[0];
    const int*   edges    = (const int*)  d_in[1];
    const float* W0       = (const float*)d_in[2];
    const float* b0       = (const float*)d_in[3];
    const float* W1       = (const float*)d_in[4];
    const float* b1       = (const float*)d_in[5];
    const float* gamma    = (const float*)d_in[6];
    const float* beta     = (const float*)d_in[7];
    float* out = (float*)d_out;

    int V = in_sizes[0] / D;
    int E = in_sizes[1] / 2;
    float invV = 1.0f / (float)V;

    // Bhi/Blo [128][KS] + Ahi/Alo [64][KS], bf16
    const int SMEM_BYTES = (2 * 128 + 2 * TM_ROWS) * KS * 2;   // 104448
    cudaFuncSetAttribute(gemm_dual_tc, cudaFuncAttributeMaxDynamicSharedMemorySize, SMEM_BYTES);

    float* statsP = nullptr;
    cudaGetSymbolAddress((void**)&statsP, g_stats);

    zero_kernel<<<(V + 255) / 256, 256>>>(V);
    build_adj<<<(E + 255) / 256, 256>>>(edges, E);
    dinv_kernel<<<(V + 255) / 256, 256>>>(V);

    for (int l = 0; l < 3; l++) {
        const float* gPrev = (l == 0) ? nullptr : gamma + (size_t)(l - 1) * D;
        const float* bPrev = (l == 0) ? nullptr : beta  + (size_t)(l - 1) * D;
        gemm_dual_tc<<<296, TC_THR, SMEM_BYTES>>>(
            features, l,
            W0 + (size_t)l * D * D, b0 + (size_t)l * D,
            W1 + (size_t)l * D * D, b1 + (size_t)l * D,
            gPrev, bPrev, V, invV);

        agg_kernel<<<592, 256>>>(statsP + l * 2 * D, V);
    }

    norm_final<<<592, 256>>>(statsP + 2 * 2 * D,
                             gamma + 2 * (size_t)D, beta + 2 * (size_t)D,
                             features, out, V, invV);
}

// round 10
// speedup vs baseline: 1.1752x; 1.1752x over previous
#include <cuda_runtime.h>
#include <cuda_fp16.h>
#include <cstdint>

#define D 128
#define VCAP 100000
#define CAP 128
#define TM_ROWS 96         // rows per tensor tile (M)
#define TC_THR 384         // 12 warps: 3 row groups (32 rows) x 4 col groups (64 cols)
#define KS 136             // fp16 row stride (128 + 8 pad) -> conflict-free LDSM

// ---------------- scratch ----------------
__device__ float g_h0[(size_t)VCAP * D];
__device__ float g_h1[(size_t)VCAP * D];
__device__ float g_y [(size_t)VCAP * D];
__device__ int   g_adj[(size_t)VCAP * CAP];
__device__ int   g_cnt[VCAP];
__device__ float g_dinv[VCAP];
__device__ float g_stats[3 * 2 * D];

// ---------------- helpers ----------------
__device__ __forceinline__ uint32_t smem_u32(const void* p) {
    return (uint32_t)__cvta_generic_to_shared(p);
}
// pack two f32 -> f16x2 (a -> lo, b -> hi)
__device__ __forceinline__ uint32_t pack_h2(float a, float b) {
    uint32_t r;
    asm("cvt.rn.f16x2.f32 %0, %1, %2;" : "=r"(r) : "f"(b), "f"(a));
    return r;
}
__device__ __forceinline__ void ldsm_x4(uint32_t addr, uint32_t r[4]) {
    asm volatile("ldmatrix.sync.aligned.m8n8.x4.shared.b16 {%0,%1,%2,%3}, [%4];"
                 : "=r"(r[0]), "=r"(r[1]), "=r"(r[2]), "=r"(r[3]) : "r"(addr));
}
__device__ __forceinline__ void mma_f16(float c[4], const uint32_t a[4],
                                        uint32_t b0, uint32_t b1) {
    asm volatile(
        "mma.sync.aligned.m16n8k16.row.col.f32.f16.f16.f32 "
        "{%0,%1,%2,%3}, {%4,%5,%6,%7}, {%8,%9}, {%0,%1,%2,%3};"
        : "+f"(c[0]), "+f"(c[1]), "+f"(c[2]), "+f"(c[3])
        : "r"(a[0]), "r"(a[1]), "r"(a[2]), "r"(a[3]), "r"(b0), "r"(b1));
}

// ---------------- prologue kernels ----------------
__global__ void zero_kernel(int V) {
    int i = blockIdx.x * blockDim.x + threadIdx.x;
    if (i < V) g_cnt[i] = 0;
    if (i < 3 * 2 * D) g_stats[i] = 0.0f;
}

__global__ void build_adj(const int* __restrict__ edges, int E) {
    int e = blockIdx.x * blockDim.x + threadIdx.x;
    if (e >= E) return;
    int a = edges[2 * e];
    int b = edges[2 * e + 1];
    int pa = atomicAdd(&g_cnt[a], 1);
    if (pa < CAP) g_adj[(size_t)a * CAP + pa] = b;
    int pb = atomicAdd(&g_cnt[b], 1);
    if (pb < CAP) g_adj[(size_t)b * CAP + pb] = a;
}

__global__ void dinv_kernel(int V) {
    int i = blockIdx.x * blockDim.x + threadIdx.x;
    if (i < V) g_dinv[i] = 1.0f / (1.0f + (float)g_cnt[i]);
}

// ---------------- HMMA dual GEMM (fp16, 2 terms: x_h*W_hi + x_h*W_lo) ----------------
// h0 = f(x) @ W0^T + b0 ; h1 = f(x) @ W1^T + b1 ; f = BN+ReLU of prev layer (l>0)
__global__ void __launch_bounds__(TC_THR, 1)
gemm_dual_tc(const float* __restrict__ xext, int layer,
             const float* __restrict__ W0, const float* __restrict__ b0,
             const float* __restrict__ W1, const float* __restrict__ b1,
             const float* __restrict__ gammaPrev, const float* __restrict__ betaPrev,
             int V, float invV)
{
    extern __shared__ __align__(16) char smb[];
    __half* Bhi = (__half*)smb;                       // [256][KS]
    __half* Blo = Bhi + 256 * KS;                     // [256][KS]
    __half* Ah  = Blo + 256 * KS;                     // [96][KS]

    __shared__ float s_sc[D], s_sh[D], s_bias[256];

    const float* x = (layer == 0) ? xext : g_y;
    const bool doNorm = (layer != 0);

    int tid  = threadIdx.x;
    int wid  = tid >> 5;
    int lane = tid & 31;

    if (tid < D) {
        if (doNorm) {
            const float* st = g_stats + (layer - 1) * 2 * D;
            float mu  = st[tid] * invV;
            float var = st[D + tid] * invV - mu * mu;
            float rs  = rsqrtf(var + 1e-5f);
            float sc  = gammaPrev[tid] * rs;
            s_sc[tid] = sc;
            s_sh[tid] = betaPrev[tid] - mu * sc;
        }
        s_bias[tid]     = b0[tid];
        s_bias[tid + D] = b1[tid];
    }

    // --- convert W0||W1 -> Bhi/Blo (fp16 hi + residual lo, once per block) ---
    for (int idx = tid; idx < 256 * 32; idx += TC_THR) {
        int n  = idx >> 5;
        int k4 = (idx & 31) * 4;
        const float* Wp = (n < D) ? (W0 + (size_t)n * D + k4)
                                  : (W1 + (size_t)(n - D) * D + k4);
        float4 w = *(const float4*)Wp;
        float h0 = __half2float(__float2half_rn(w.x));
        float h1 = __half2float(__float2half_rn(w.y));
        float h2 = __half2float(__float2half_rn(w.z));
        float h3 = __half2float(__float2half_rn(w.w));
        *(uint2*)(Bhi + n * KS + k4) = make_uint2(pack_h2(h0, h1), pack_h2(h2, h3));
        *(uint2*)(Blo + n * KS + k4) = make_uint2(pack_h2(w.x - h0, w.y - h1),
                                                  pack_h2(w.z - h2, w.w - h3));
    }

    // warp tiling: mw = row group (32 rows, 0..2), nw = col group (64 cols, 0..3)
    int mw = wid >> 2;
    int nw = wid & 3;
    int mrow0 = mw * 32;
    int ncolbase = nw * 64;     // within 0..255

    // A ldmatrix addresses: two 16-row sets
    uint32_t aOffB = (uint32_t)(((mrow0 + (lane & 15)) * KS + (lane >> 4) * 8) * 2);
    uint32_t aAddr0 = smem_u32(Ah) + aOffB;
    uint32_t aAddr1 = aAddr0 + 16 * KS * 2;

    // B ldmatrix x4 addresses: 16 n-rows per load (2 n-groups of 8)
    uint32_t bOffB = (uint32_t)(((ncolbase + (lane & 15)) * KS + (lane >> 4) * 8) * 2);
    uint32_t bHiAddr = smem_u32(Bhi) + bOffB;
    uint32_t bLoAddr = smem_u32(Blo) + bOffB;

    int ncol = (lane & 3) * 2;

    int numTiles = (V + TM_ROWS - 1) / TM_ROWS;
    int tFirst = blockIdx.x;

    // --- register prefetch of first tile ---
    float4 pf[8];
    {
        int r0 = tFirst * TM_ROWS;
        #pragma unroll
        for (int it = 0; it < 8; it++) {
            int f   = tid + it * TC_THR;
            int row = r0 + (f >> 5);
            int k4  = (f & 31) * 4;
            pf[it] = (tFirst < numTiles && row < V)
                   ? *(const float4*)(x + (size_t)row * D + k4)
                   : make_float4(0.f, 0.f, 0.f, 0.f);
        }
    }

    for (int t = tFirst; t < numTiles; t += gridDim.x) {
        int r0 = t * TM_ROWS;

        // --- convert prefetched x tile -> Ah (fused BN+ReLU for layers 1,2) ---
        #pragma unroll
        for (int it = 0; it < 8; it++) {
            int f  = tid + it * TC_THR;
            int r  = f >> 5;
            int k4 = (f & 31) * 4;
            float4 a = pf[it];
            if (doNorm) {
                a.x = fmaxf(fmaf(a.x, s_sc[k4 + 0], s_sh[k4 + 0]), 0.f);
                a.y = fmaxf(fmaf(a.y, s_sc[k4 + 1], s_sh[k4 + 1]), 0.f);
                a.z = fmaxf(fmaf(a.z, s_sc[k4 + 2], s_sh[k4 + 2]), 0.f);
                a.w = fmaxf(fmaf(a.w, s_sc[k4 + 3], s_sh[k4 + 3]), 0.f);
                if (r0 + r >= V) a = make_float4(0.f, 0.f, 0.f, 0.f);
            }
            *(uint2*)(Ah + r * KS + k4) = make_uint2(pack_h2(a.x, a.y), pack_h2(a.z, a.w));
        }
        __syncthreads();

        // --- prefetch next tile (latency hidden under MMA loop) ---
        int tn = t + gridDim.x;
        if (tn < numTiles) {
            int rn0 = tn * TM_ROWS;
            #pragma unroll
            for (int it = 0; it < 8; it++) {
                int f   = tid + it * TC_THR;
                int row = rn0 + (f >> 5);
                int k4  = (f & 31) * 4;
                pf[it] = (row < V) ? *(const float4*)(x + (size_t)row * D + k4)
                                   : make_float4(0.f, 0.f, 0.f, 0.f);
            }
        }

        // --- accumulators init to bias: acc[n][0..3] rowset0, [4..7] rowset1 ---
        float acc[8][8];
        #pragma unroll
        for (int n = 0; n < 8; n++) {
            float bx = s_bias[ncolbase + n * 8 + ncol];
            float by = s_bias[ncolbase + n * 8 + ncol + 1];
            acc[n][0] = bx; acc[n][1] = by; acc[n][2] = bx; acc[n][3] = by;
            acc[n][4] = bx; acc[n][5] = by; acc[n][6] = bx; acc[n][7] = by;
        }

        // --- main MMA loop: 8 k-chunks, 2 terms ---
        #pragma unroll
        for (int kc = 0; kc < 8; kc++) {
            uint32_t a0[4], a1[4];
            ldsm_x4(aAddr0 + kc * 32, a0);
            ldsm_x4(aAddr1 + kc * 32, a1);
            #pragma unroll
            for (int np = 0; np < 4; np++) {
                uint32_t bhi[4], blo[4];
                uint32_t boff = (uint32_t)(np * 16 * KS * 2 + kc * 32);
                ldsm_x4(bHiAddr + boff, bhi);
                ldsm_x4(bLoAddr + boff, blo);
                float* aE = acc[np * 2];
                float* aO = acc[np * 2 + 1];
                mma_f16(aE,     a0, bhi[0], bhi[2]);
                mma_f16(aE,     a0, blo[0], blo[2]);
                mma_f16(aO,     a0, bhi[1], bhi[3]);
                mma_f16(aO,     a0, blo[1], blo[3]);
                mma_f16(aE + 4, a1, bhi[0], bhi[2]);
                mma_f16(aE + 4, a1, blo[0], blo[2]);
                mma_f16(aO + 4, a1, bhi[1], bhi[3]);
                mma_f16(aO + 4, a1, blo[1], blo[3]);
            }
        }

        // --- epilogue: store to g_h0 / g_h1 ---
        int rA = r0 + mrow0 + (lane >> 2);
        float* dst = (nw < 2) ? g_h0 : g_h1;
        int cb = (nw & 1) * 64;
        #pragma unroll
        for (int n = 0; n < 8; n++) {
            int c = cb + n * 8 + ncol;
            if (rA < V)      *(float2*)(dst + (size_t)rA * D + c)        = make_float2(acc[n][0], acc[n][1]);
            if (rA + 8 < V)  *(float2*)(dst + (size_t)(rA + 8) * D + c)  = make_float2(acc[n][2], acc[n][3]);
            if (rA + 16 < V) *(float2*)(dst + (size_t)(rA + 16) * D + c) = make_float2(acc[n][4], acc[n][5]);
            if (rA + 24 < V) *(float2*)(dst + (size_t)(rA + 24) * D + c) = make_float2(acc[n][6], acc[n][7]);
        }
        __syncthreads();   // MMA readers done before next conversion overwrites A
    }
}

// ---------------- aggregation + BN stats ----------------
__global__ void __launch_bounds__(256) agg_kernel(float* __restrict__ stats, int V)
{
    __shared__ float s_sum[D];
    __shared__ float s_sq[D];

    int tid  = threadIdx.x;
    int wid  = tid >> 5;
    int lane = tid & 31;
    int c0   = lane * 4;

    if (tid < D) { s_sum[tid] = 0.f; s_sq[tid] = 0.f; }
    __syncthreads();

    float4 psum = make_float4(0.f, 0.f, 0.f, 0.f);
    float4 psq  = make_float4(0.f, 0.f, 0.f, 0.f);

    int warpStride = gridDim.x * 8;
    for (int v = blockIdx.x * 8 + wid; v < V; v += warpStride) {
        float4 acc = *(const float4*)(g_h0 + (size_t)v * D + c0);
        int n = g_cnt[v];
        const int* ap = g_adj + (size_t)v * CAP;
        int e = 0;
        for (; e + 3 < n; e += 4) {
            int u0 = ap[e], u1 = ap[e + 1], u2 = ap[e + 2], u3 = ap[e + 3];
            float4 t0 = __ldg((const float4*)(g_h1 + (size_t)u0 * D + c0));
            float4 t1 = __ldg((const float4*)(g_h1 + (size_t)u1 * D + c0));
            float4 t2 = __ldg((const float4*)(g_h1 + (size_t)u2 * D + c0));
            float4 t3 = __ldg((const float4*)(g_h1 + (size_t)u3 * D + c0));
            acc.x += (t0.x + t1.x) + (t2.x + t3.x);
            acc.y += (t0.y + t1.y) + (t2.y + t3.y);
            acc.z += (t0.z + t1.z) + (t2.z + t3.z);
            acc.w += (t0.w + t1.w) + (t2.w + t3.w);
        }
        for (; e < n; e++) {
            int u = ap[e];
            float4 t = __ldg((const float4*)(g_h1 + (size_t)u * D + c0));
            acc.x += t.x; acc.y += t.y; acc.z += t.z; acc.w += t.w;
        }
        float dv = g_dinv[v];
        acc.x *= dv; acc.y *= dv; acc.z *= dv; acc.w *= dv;
        *(float4*)(g_y + (size_t)v * D + c0) = acc;

        psum.x += acc.x; psum.y += acc.y; psum.z += acc.z; psum.w += acc.w;
        psq.x  += acc.x * acc.x; psq.y += acc.y * acc.y;
        psq.z  += acc.z * acc.z; psq.w += acc.w * acc.w;
    }

    atomicAdd(&s_sum[c0 + 0], psum.x);
    atomicAdd(&s_sum[c0 + 1], psum.y);
    atomicAdd(&s_sum[c0 + 2], psum.z);
    atomicAdd(&s_sum[c0 + 3], psum.w);
    atomicAdd(&s_sq[c0 + 0],  psq.x);
    atomicAdd(&s_sq[c0 + 1],  psq.y);
    atomicAdd(&s_sq[c0 + 2],  psq.z);
    atomicAdd(&s_sq[c0 + 3],  psq.w);
    __syncthreads();

    if (tid < D) {
        atomicAdd(&stats[tid],     s_sum[tid]);
        atomicAdd(&stats[D + tid], s_sq[tid]);
    }
}

// ---------------- final BN + ReLU + residual -> out ----------------
__global__ void __launch_bounds__(256) norm_final(
    const float* __restrict__ stats,
    const float* __restrict__ gamma, const float* __restrict__ beta,
    const float* __restrict__ res,
    float* __restrict__ out, int V, float invV)
{
    __shared__ float s_scale[D];
    __shared__ float s_shift[D];

    int tid = threadIdx.x;
    if (tid < D) {
        float mu  = stats[tid] * invV;
        float var = stats[D + tid] * invV - mu * mu;
        float rs  = rsqrtf(var + 1e-5f);
        float sc  = gamma[tid] * rs;
        s_scale[tid] = sc;
        s_shift[tid] = beta[tid] - mu * sc;
    }
    __syncthreads();

    int total = V * (D / 4);
    for (int f = blockIdx.x * blockDim.x + tid; f < total; f += gridDim.x * blockDim.x) {
        int c = (f & 31) * 4;
        float4 t = *(const float4*)(g_y + (size_t)f * 4);
        float4 r = *(const float4*)(res + (size_t)f * 4);
        float4 o;
        o.x = fmaxf(fmaf(t.x, s_scale[c + 0], s_shift[c + 0]) + r.x, 0.f);
        o.y = fmaxf(fmaf(t.y, s_scale[c + 1], s_shift[c + 1]) + r.y, 0.f);
        o.z = fmaxf(fmaf(t.z, s_scale[c + 2], s_shift[c + 2]) + r.z, 0.f);
        o.w = fmaxf(fmaf(t.w, s_scale[c + 3], s_shift[c + 3]) + r.w, 0.f);
        *(float4*)(out + (size_t)f * 4) = o;
    }
}

// ---------------- launch ----------------
extern "C" void kernel_launch(void* const* d_in, const int* in_sizes, int n_in,
                              void* d_out, int out_size)
{
    const float* features = (const float*)d_in[0];
    const int*   edges    = (const int*)  d_in[1];
    const float* W0       = (const float*)d_in[2];
    const float* b0       = (const float*)d_in[3];
    const float* W1       = (const float*)d_in[4];
    const float* b1       = (const float*)d_in[5];
    const float* gamma    = (const float*)d_in[6];
    const float* beta     = (const float*)d_in[7];
    float* out = (float*)d_out;

    int V = in_sizes[0] / D;
    int E = in_sizes[1] / 2;
    float invV = 1.0f / (float)V;

    // Bhi/Blo [256][KS] + Ah [96][KS], fp16
    const int SMEM_BYTES = (2 * 256 + TM_ROWS) * KS * 2;
    cudaFuncSetAttribute(gemm_dual_tc, cudaFuncAttributeMaxDynamicSharedMemorySize, SMEM_BYTES);

    float* statsP = nullptr;
    cudaGetSymbolAddress((void**)&statsP, g_stats);

    zero_kernel<<<(V + 255) / 256, 256>>>(V);
    build_adj<<<(E + 255) / 256, 256>>>(edges, E);
    dinv_kernel<<<(V + 255) / 256, 256>>>(V);

    for (int l = 0; l < 3; l++) {
        const float* gPrev = (l == 0) ? nullptr : gamma + (size_t)(l - 1) * D;
        const float* bPrev = (l == 0) ? nullptr : beta  + (size_t)(l - 1) * D;
        gemm_dual_tc<<<148, TC_THR, SMEM_BYTES>>>(
            features, l,
            W0 + (size_t)l * D * D, b0 + (size_t)l * D,
            W1 + (size_t)l * D * D, b1 + (size_t)l * D,
            gPrev, bPrev, V, invV);

        agg_kernel<<<1184, 256>>>(statsP + l * 2 * D, V);
    }

    norm_final<<<1184, 256>>>(statsP + 2 * 2 * D,
                              gamma + 2 * (size_t)D, beta + 2 * (size_t)D,
                              features, out, V, invV);
}